// round 5
// baseline (speedup 1.0000x reference)
#include <cuda_runtime.h>

#define W 224
#define H 224
#define BC 192
#define STEPS 32
#define BANDS 8
#define RPB 28
#define TPB 128
#define NW 4
#define GRID (BC * BANDS)

// g_hist[bc][j] accumulates cumulative Euler characteristic at t_j directly.
__device__ int g_hist[BC * STEPS];
__device__ unsigned int g_count;

// Alive mask for searchsorted(linspace(0,1,32), f, 'left'): bit j set iff t_j >= f.
// Bit-exact vs reference (rel_err == 0 in R1/R2/R4).
__device__ __forceinline__ unsigned maskof(float f) {
    const float step = 1.0f / 31.0f;
    int g = __float2int_ru(f * 31.0f);                 // g in [0,31] for f in [0,1)
    if ((float)(g - 1) * step >= f) g--;               // g=0: -step >= f(>=0) never
    if (g < 31 && (float)g * step < f) g++;            // t_31 = 1.0 >= f always
    return 0xFFFFFFFFu << g;
}

__device__ __forceinline__ void csa5(unsigned c[5], unsigned x) {
    unsigned t;
    t = c[0] & x; c[0] ^= x; x = t;
    t = c[1] & x; c[1] ^= x; x = t;
    t = c[2] & x; c[2] ^= x; x = t;
    t = c[3] & x; c[3] ^= x; x = t;
    c[4] ^= x;
}
__device__ __forceinline__ void csa4(unsigned c[4], unsigned x) {
    unsigned t;
    t = c[0] & x; c[0] ^= x; x = t;
    t = c[1] & x; c[1] ^= x; x = t;
    t = c[2] & x; c[2] ^= x; x = t;
    c[3] ^= x;
}

// Add 4 one-bit masks via 4:2 compressor into weighted accumulators
// A (w1, csa5), B (w2, csa4), C (w4, csa4).
__device__ __forceinline__ void add4(unsigned A[5], unsigned B[4], unsigned C[4],
                                     unsigned x1, unsigned x2, unsigned x3, unsigned x4) {
    unsigned s1 = x1 ^ x2 ^ x3;                         // LOP3 0x96
    unsigned c1 = (x1 & x2) | (x1 & x3) | (x2 & x3);    // LOP3 0xE8 (majority)
    unsigned s2 = s1 ^ x4;
    unsigned c2 = s1 & x4;
    unsigned s3 = c1 ^ c2;
    unsigned c3 = c1 & c2;
    csa5(A, s2);
    csa4(B, s3);
    csa4(C, c3);
}

// Warp 32x32 bit-matrix transpose: out lane j bit k = in lane k bit j.
__device__ __forceinline__ unsigned tr32(unsigned v, int lane) {
    unsigned w;
    w = __shfl_xor_sync(0xffffffffu, v, 16);
    v = (lane & 16) ? ((v & 0xFFFF0000u) | ((w >> 16) & 0x0000FFFFu))
                    : ((v & 0x0000FFFFu) | ((w << 16) & 0xFFFF0000u));
    w = __shfl_xor_sync(0xffffffffu, v, 8);
    v = (lane & 8)  ? ((v & 0xFF00FF00u) | ((w >> 8)  & 0x00FF00FFu))
                    : ((v & 0x00FF00FFu) | ((w << 8)  & 0xFF00FF00u));
    w = __shfl_xor_sync(0xffffffffu, v, 4);
    v = (lane & 4)  ? ((v & 0xF0F0F0F0u) | ((w >> 4)  & 0x0F0F0F0Fu))
                    : ((v & 0x0F0F0F0Fu) | ((w << 4)  & 0xF0F0F0F0u));
    w = __shfl_xor_sync(0xffffffffu, v, 2);
    v = (lane & 2)  ? ((v & 0xCCCCCCCCu) | ((w >> 2)  & 0x33333333u))
                    : ((v & 0x33333333u) | ((w << 2)  & 0xCCCCCCCCu));
    w = __shfl_xor_sync(0xffffffffu, v, 1);
    v = (lane & 1)  ? ((v & 0xAAAAAAAAu) | ((w >> 1)  & 0x55555555u))
                    : ((v & 0x55555555u) | ((w << 1)  & 0xAAAAAAAAu));
    return v;
}

// Lane owns columns a (even) and b=a+1. Warp w covers pixel cols [62w, 62w+61].
// eB: b == 223 (edge column). aM: lane produces pixels at all.
__global__ __launch_bounds__(TPB) void ecc_kernel(const float* __restrict__ x,
                                                  float* __restrict__ out) {
    __shared__ int s_cnt[NW][STEPS];
    __shared__ bool s_last;

    const int tid  = threadIdx.x;
    const int wid  = tid >> 5;
    const int lane = tid & 31;
    const int bc   = blockIdx.x >> 3;
    const int band = blockIdx.x & 7;
    const int r0   = band * RPB;
    const int a    = 62 * wid + 2 * lane;

    const bool act      = (lane < 31) && (a <= 222);
    const unsigned aM   = act ? 0xFFFFFFFFu : 0u;
    const unsigned eB   = (a == 222) ? 0xFFFFFFFFu : 0u;   // b == 223
    const int cl        = (a <= 222) ? a : 222;            // clamped, stays 8B-aligned
    const float* p = x + (size_t)bc * (H * W) + (size_t)r0 * W + cl;

    unsigned AP[5] = {0,0,0,0,0}, BP[4] = {0,0,0,0}, CP[4] = {0,0,0,0};
    unsigned AN[5] = {0,0,0,0,0}, BN[4] = {0,0,0,0}, CN[4] = {0,0,0,0};

    float2 v0 = __ldg((const float2*)p);
    unsigned m0 = maskof(v0.x), m1 = maskof(v0.y);
    unsigned m0n = __shfl_down_sync(0xffffffffu, m0, 1);

    const int nit = (band == BANDS - 1) ? 13 : 14;
#pragma unroll 2
    for (int it = 0; it < nit; it++) {
        float2 vn = __ldg((const float2*)(p + W));
        float2 vp = __ldg((const float2*)(p + 2 * W));
        p += 2 * W;
        unsigned n0 = maskof(vn.x), n1 = maskof(vn.y);
        unsigned q0 = maskof(vp.x), q1 = maskof(vp.y);
        unsigned n0n = __shfl_down_sync(0xffffffffu, n0, 1);
        unsigned q0n = __shfl_down_sync(0xffffffffu, q0, 1);

        // pixel row r: masks m over n
        unsigned mrB  = (m0n & ~eB) | (n1 & eB);   // edge col: mr := below
        unsigned mnrB = n0n | eB;                  // edge col: mnr := all-ones
        unsigned ta = m1 & n1;
        unsigned tb = mrB & mnrB;
        unsigned Pa = m0 & ~m1 & aM;
        unsigned Pb = m1 & ~mrB & aM;
        unsigned Na = (m0 & n0) & ~ta & aM;
        unsigned Nb = ta & ~tb & aM;
        // pixel row r+1: masks n over q
        unsigned nrB  = (n0n & ~eB) | (q1 & eB);
        unsigned nnrB = q0n | eB;
        unsigned ua = n1 & q1;
        unsigned ub = nrB & nnrB;
        unsigned Qa = n0 & ~n1 & aM;
        unsigned Qb = n1 & ~nrB & aM;
        unsigned Ma = (n0 & q0) & ~ua & aM;
        unsigned Mb = ua & ~ub & aM;

        add4(AP, BP, CP, Pa, Pb, Qa, Qb);
        add4(AN, BN, CN, Na, Nb, Ma, Mb);

        m0 = q0; m1 = q1; m0n = q0n;
    }

    if (band == BANDS - 1) {
        // tail: pixel row 222 (full) + pixel row 223 (vertex + h-edge only)
        float2 vn = __ldg((const float2*)(p + W));              // row 223
        unsigned n0 = maskof(vn.x), n1 = maskof(vn.y);
        unsigned n0n = __shfl_down_sync(0xffffffffu, n0, 1);
        unsigned mrB  = (m0n & ~eB) | (n1 & eB);
        unsigned mnrB = n0n | eB;
        unsigned ta = m1 & n1;
        unsigned tb = mrB & mnrB;
        unsigned Pa = m0 & ~m1 & aM;
        unsigned Pb = m1 & ~mrB & aM;
        unsigned Na = (m0 & n0) & ~ta & aM;
        unsigned Nb = ta & ~tb & aM;
        // bottom row: P = m & ~mr, corner (223,223): P = m  (mr := 0)
        unsigned brB = n0n & ~eB;
        unsigned Ra = n0 & ~n1 & aM;
        unsigned Rb = n1 & ~brB & aM;
        add4(AP, BP, CP, Pa, Pb, Ra, Rb);
        unsigned s = Na ^ Nb, c = Na & Nb;
        csa5(AN, s);
        csa4(BN, c);
    }

    // Epilogue: transpose planes, weighted popcounts -> chi contribution @bin lane.
    int cnt = 0;
#pragma unroll
    for (int i = 0; i < 5; i++) cnt += (int)__popc(tr32(AP[i], lane)) << i;
#pragma unroll
    for (int i = 0; i < 4; i++) cnt += (int)__popc(tr32(BP[i], lane)) << (i + 1);
#pragma unroll
    for (int i = 0; i < 4; i++) cnt += (int)__popc(tr32(CP[i], lane)) << (i + 2);
#pragma unroll
    for (int i = 0; i < 5; i++) cnt -= (int)__popc(tr32(AN[i], lane)) << i;
#pragma unroll
    for (int i = 0; i < 4; i++) cnt -= (int)__popc(tr32(BN[i], lane)) << (i + 1);
#pragma unroll
    for (int i = 0; i < 4; i++) cnt -= (int)__popc(tr32(CN[i], lane)) << (i + 2);

    s_cnt[wid][lane] = cnt;
    __syncthreads();
    if (wid == 0) {
        int sum = s_cnt[0][lane] + s_cnt[1][lane] + s_cnt[2][lane] + s_cnt[3][lane];
        atomicAdd(&g_hist[bc * STEPS + lane], sum);
    }

    // Last-block-done: write out + reset scratch for next graph replay.
    __threadfence();
    __syncthreads();
    if (tid == 0)
        s_last = (atomicAdd(&g_count, 1u) == (unsigned)(GRID - 1));
    __syncthreads();

    if (s_last) {
        __threadfence();
        for (int g2 = wid; g2 < BC; g2 += NW) {
            const int vv = __ldcg(&g_hist[g2 * STEPS + lane]);
            out[g2 * STEPS + lane] = (float)vv;
            g_hist[g2 * STEPS + lane] = 0;
        }
        if (tid == 0) g_count = 0u;
    }
}

extern "C" void kernel_launch(void* const* d_in, const int* in_sizes, int n_in,
                              void* d_out, int out_size) {
    const float* x = (const float*)d_in[0];
    float* out = (float*)d_out;
    (void)in_sizes; (void)n_in; (void)out_size;
    ecc_kernel<<<GRID, TPB>>>(x, out);
}

// round 6
// speedup vs baseline: 1.1646x; 1.1646x over previous
#include <cuda_runtime.h>

#define W 224
#define H 224
#define BC 192
#define STEPS 32
#define BANDS 4
#define RPB 56
#define TPB 256
#define NW 8
#define GRID (BC * BANDS)   // 768 ~= one wave of 148 SMs * 5-6 blocks

// g_hist[bc][j] accumulates the cumulative Euler characteristic at t_j.
__device__ int g_hist[BC * STEPS];
__device__ unsigned int g_count;

// Alive mask: bit j set iff t_j >= f, t_j = fl(j * fl(1/31)) (j<31), t_31 = 1.
// fr = ceilf(31f) is within 1 of the true bin; fixups compare f against the
// EXACT grid values: FFMA(fr,step,-step) == fl((fr-1)*step) since
// fr*step - step == (fr-1)*step in exact arithmetic (fr integral). Bit-exact.
__device__ __forceinline__ unsigned maskof(float f) {
    const float step = 1.0f / 31.0f;
    float fr = ceilf(f * 31.0f);                 // integral, in [0, 31]
    int g = (int)fr;
    if (__fmaf_rn(fr, step, -step) >= f) g--;    // t_{fr-1} >= f
    if (fr < 31.0f && fr * step < f)     g++;    // t_fr < f (t_31=1.0 >= f always)
    return 0xFFFFFFFFu << g;
}

__device__ __forceinline__ void csa5(unsigned c[5], unsigned x) {
    unsigned t;
    t = c[0] & x; c[0] ^= x; x = t;
    t = c[1] & x; c[1] ^= x; x = t;
    t = c[2] & x; c[2] ^= x; x = t;
    t = c[3] & x; c[3] ^= x; x = t;
    c[4] ^= x;
}
// 3:2 full-adder into weight-1 and weight-2 plane sets.
__device__ __forceinline__ void add3(unsigned A1[5], unsigned A2[5],
                                     unsigned x, unsigned y, unsigned z) {
    unsigned s = x ^ y ^ z;
    unsigned c = (x & y) | (x & z) | (y & z);
    csa5(A1, s);
    csa5(A2, c);
}
__device__ __forceinline__ void add2(unsigned A1[5], unsigned A2[5],
                                     unsigned x, unsigned y) {
    csa5(A1, x ^ y);
    csa5(A2, x & y);
}

// Warp 32x32 bit transpose: out lane j bit k = in lane k bit j.
__device__ __forceinline__ unsigned tr32(unsigned v, int lane) {
    unsigned w;
    w = __shfl_xor_sync(0xffffffffu, v, 16);
    v = (lane & 16) ? ((v & 0xFFFF0000u) | ((w >> 16) & 0x0000FFFFu))
                    : ((v & 0x0000FFFFu) | ((w << 16) & 0xFFFF0000u));
    w = __shfl_xor_sync(0xffffffffu, v, 8);
    v = (lane & 8)  ? ((v & 0xFF00FF00u) | ((w >> 8)  & 0x00FF00FFu))
                    : ((v & 0x00FF00FFu) | ((w << 8)  & 0xFF00FF00u));
    w = __shfl_xor_sync(0xffffffffu, v, 4);
    v = (lane & 4)  ? ((v & 0xF0F0F0F0u) | ((w >> 4)  & 0x0F0F0F0Fu))
                    : ((v & 0x0F0F0F0Fu) | ((w << 4)  & 0xF0F0F0F0u));
    w = __shfl_xor_sync(0xffffffffu, v, 2);
    v = (lane & 2)  ? ((v & 0xCCCCCCCCu) | ((w >> 2)  & 0x33333333u))
                    : ((v & 0x33333333u) | ((w << 2)  & 0xCCCCCCCCu));
    w = __shfl_xor_sync(0xffffffffu, v, 1);
    v = (lane & 1)  ? ((v & 0xAAAAAAAAu) | ((w >> 1)  & 0x55555555u))
                    : ((v & 0x55555555u) | ((w << 1)  & 0xAAAAAAAAu));
    return v;
}

struct St { const float* p; unsigned m, mr; };

// One pixel row: emits P (weight +1 cells: vertex/h-edge net) and
// N (weight -1 cells: v-edge/square net) as bin bitmasks; loads row below.
//   interior: P = m & ~mr          N = (m & mn) & ~(mr & mnr)
//   edge col: P = m & ~mn          N = 0
//   inactive: P = 0 (aM)           N = 0 (hasRM)
__device__ __forceinline__ void rowPN(St& s, unsigned aM, unsigned hasRM,
                                      unsigned& P, unsigned& N, int ofs) {
    const unsigned mn  = maskof(__ldg(s.p + ofs));
    const unsigned mnr = __shfl_down_sync(0xffffffffu, mn, 1);
    const unsigned mrEff = (s.mr & hasRM) | (mn & ~hasRM);   // LOP3
    P = (s.m & ~mrEff) & aM;                                  // LOP3
    const unsigned t2 = (s.mr & mnr) | ~hasRM;                // LOP3
    N = (s.m & mn) & ~t2;                                     // LOP3
    s.m = mn; s.mr = mnr;
}

__global__ __launch_bounds__(TPB) void ecc_kernel(const float* __restrict__ x,
                                                  float* __restrict__ out) {
    __shared__ int s_cnt[NW][STEPS];
    __shared__ bool s_last;

    const int tid  = threadIdx.x;
    const int wid  = tid >> 5;
    const int lane = tid & 31;
    const int col  = wid * 31 + lane;
    const int bc   = blockIdx.x >> 2;
    const int band = blockIdx.x & 3;
    const int r0   = band * RPB;

    const bool act      = (lane < 31) && (col <= 223);
    const unsigned aM   = act ? 0xFFFFFFFFu : 0u;
    const unsigned hasRM = (act && col < 223) ? 0xFFFFFFFFu : 0u;
    const int colc = (col <= 223) ? col : 223;

    unsigned P1[5] = {0,0,0,0,0}, P2[5] = {0,0,0,0,0};
    unsigned N1[5] = {0,0,0,0,0}, N2[5] = {0,0,0,0,0};

    St s;
    s.p  = x + (size_t)bc * (H * W) + (size_t)r0 * W + colc;
    s.m  = maskof(__ldg(s.p));
    s.mr = __shfl_down_sync(0xffffffffu, s.m, 1);

    // 18 triples = 54 pixel rows (both band types).
#pragma unroll 2
    for (int it = 0; it < 18; it++) {
        unsigned Pa, Na, Pb, Nb, Pc, Nc;
        rowPN(s, aM, hasRM, Pa, Na, W);
        rowPN(s, aM, hasRM, Pb, Nb, 2 * W);
        rowPN(s, aM, hasRM, Pc, Nc, 3 * W);
        s.p += 3 * W;
        add3(P1, P2, Pa, Pb, Pc);
        add3(N1, N2, Na, Nb, Nc);
    }

    if (band != BANDS - 1) {
        // rows 54, 55 of the band (both full).
        unsigned Pa, Na, Pb, Nb;
        rowPN(s, aM, hasRM, Pa, Na, W);
        rowPN(s, aM, hasRM, Pb, Nb, 2 * W);
        add2(P1, P2, Pa, Pb);
        add2(N1, N2, Na, Nb);
    } else {
        // row 222 (full) + row 223 (vertex + h-edge only).
        unsigned Pa, Na;
        rowPN(s, aM, hasRM, Pa, Na, W);
        const unsigned Pb = (s.m & ~(s.mr & hasRM)) & aM;   // bottom row
        add2(P1, P2, Pa, Pb);
        csa5(N1, Na);
    }

    // Epilogue: transpose planes, weighted popcounts -> chi @ bin `lane`.
    int cnt = 0;
#pragma unroll
    for (int i = 0; i < 5; i++) cnt += (int)__popc(tr32(P1[i], lane)) << i;
#pragma unroll
    for (int i = 0; i < 5; i++) cnt += (int)__popc(tr32(P2[i], lane)) << (i + 1);
#pragma unroll
    for (int i = 0; i < 5; i++) cnt -= (int)__popc(tr32(N1[i], lane)) << i;
#pragma unroll
    for (int i = 0; i < 5; i++) cnt -= (int)__popc(tr32(N2[i], lane)) << (i + 1);

    s_cnt[wid][lane] = cnt;
    __syncthreads();
    if (wid == 0) {
        int sum = 0;
#pragma unroll
        for (int w2 = 0; w2 < NW; w2++) sum += s_cnt[w2][lane];
        atomicAdd(&g_hist[bc * STEPS + lane], sum);
    }

    // Last-block-done: write out + reset scratch for next graph replay.
    __threadfence();
    __syncthreads();
    if (tid == 0)
        s_last = (atomicAdd(&g_count, 1u) == (unsigned)(GRID - 1));
    __syncthreads();

    if (s_last) {
        __threadfence();
        for (int g2 = wid; g2 < BC; g2 += NW) {
            const int vv = __ldcg(&g_hist[g2 * STEPS + lane]);
            out[g2 * STEPS + lane] = (float)vv;
            g_hist[g2 * STEPS + lane] = 0;
        }
        if (tid == 0) g_count = 0u;
    }
}

extern "C" void kernel_launch(void* const* d_in, const int* in_sizes, int n_in,
                              void* d_out, int out_size) {
    const float* x = (const float*)d_in[0];
    float* out = (float*)d_out;
    (void)in_sizes; (void)n_in; (void)out_size;
    ecc_kernel<<<GRID, TPB>>>(x, out);
}